// round 11
// baseline (speedup 1.0000x reference)
#include <cuda_runtime.h>
#include <cstdint>

typedef unsigned long long u64;

#define VOCAB   10000
#define EMB     256
#define UNITS   128
#define NG      512        // 4 * UNITS, gate order i,f,c,o
#define BATCH   256
#define SEQ     1024

// Wr k-split: rows [0,KR) in registers, [KR,128) in shared memory
#define KR      72
#define KRP     36         // KR/2 f32x2 pairs
#define KS      56
#define KSP     28         // KS/2
#define SB      4          // smem weight double-buffer block (pairs)
#define NSB     (KSP / SB) // 7 blocks

#define NTHREADS 256
#define NBLOCKS  128       // 2 batch rows per block, one wave

// Precomputed gate table: G[v][c] = sum_e emb[v][e]*Wk[e][c] + b[c]  (20.5 MB)
__device__ float g_G[VOCAB * NG];

// ---------------- f32x2 helpers ----------------
__device__ __forceinline__ u64 fma2(u64 a, u64 b, u64 c) {
    u64 d;
    asm("fma.rn.f32x2 %0, %1, %2, %3;" : "=l"(d) : "l"(a), "l"(b), "l"(c));
    return d;
}
__device__ __forceinline__ u64 pk2(float x, float y) {
    u64 r;
    asm("mov.b64 %0, {%1, %2};" : "=l"(r) : "f"(x), "f"(y));
    return r;
}
__device__ __forceinline__ float2 upk2(u64 v) {
    float2 r;
    asm("mov.b64 {%0, %1}, %2;" : "=f"(r.x), "=f"(r.y) : "l"(v));
    return r;
}
__device__ __forceinline__ float sigmoidf(float x) {
    return __fdividef(1.0f, 1.0f + __expf(-x));
}

// ---------------- Kernel 1: G = emb @ Wk + b ----------------
#define VB 16
__global__ void __launch_bounds__(512)
gbuild_kernel(const float* __restrict__ emb, const float* __restrict__ Wk,
              const float* __restrict__ b)
{
    __shared__ float es[VB][EMB];
    const int c  = threadIdx.x;
    const int v0 = blockIdx.x * VB;

    for (int i = c; i < VB * EMB; i += 512)
        es[i / EMB][i % EMB] = emb[v0 * EMB + i];
    __syncthreads();

    float acc[VB];
#pragma unroll
    for (int v = 0; v < VB; v++) acc[v] = 0.0f;

    for (int e = 0; e < EMB; e += 4) {
        const float w0 = Wk[(e + 0) * NG + c];
        const float w1 = Wk[(e + 1) * NG + c];
        const float w2 = Wk[(e + 2) * NG + c];
        const float w3 = Wk[(e + 3) * NG + c];
#pragma unroll
        for (int v = 0; v < VB; v++) {
            float4 ev = *(const float4*)&es[v][e];
            acc[v] += ev.x * w0 + ev.y * w1 + ev.z * w2 + ev.w * w3;
        }
    }
    const float bc = b[c];
#pragma unroll
    for (int v = 0; v < VB; v++)
        g_G[(v0 + v) * NG + c] = acc[v] + bc;
}

// ---------------- Kernel 2: persistent LSTM recurrence ----------------
// R9 structure (2 rows/CTA, 256 thr; thread j: u=j>>1, p=j&1 owning gate
// cols 128p+u and 128(p+2)+u; shfl.xor(1) gate exchange; double-buffered
// interleaved h; one __syncthreads/step; 2-chunk REG/SMEM stagger across
// the SMSP partner warps) with:
//  - KR 80->72: 16 registers freed for scheduling
//  - explicit double-buffered smem-weight blocks (SB=4 pairs): block b+1's
//    weight LDS issue while block b's fma2 execute -> ~32-cyc load->use
//    distance hides the 29-cyc LDS latency.
#define WS_BYTES (KSP * NTHREADS * 16)   // 114688 B
#define HB_OFF   WS_BYTES                // 2 bufs x 128 u64 = 2048 B
#define XS_OFF   (HB_OFF + 2048)
#define SMEM_TOTAL (XS_OFF + 2 * SEQ * 4)

__global__ void __launch_bounds__(NTHREADS, 1)
lstm_kernel(const int* __restrict__ x, const float* __restrict__ Wr,
            const float* __restrict__ Wd, const float* __restrict__ bd,
            float* __restrict__ out)
{
    extern __shared__ char smem[];
    ulonglong2* W2  = (ulonglong2*)smem;            // [KSP][256]
    u64*       hbuf = (u64*)(smem + HB_OFF);        // [2][128] u64
    int*       xs   = (int*)(smem + XS_OFF);

    const int j   = threadIdx.x;
    const int blk = blockIdx.x;
    const int u   = j >> 1;
    const int p   = j & 1;
    const int cA  = 128 * p + u;          // gate p
    const int cB  = 128 * (p + 2) + u;    // gate p+2
    const bool smemFirst = (j >= 128);    // warps 4-7 start with SMEM section

    // ---- one-time setup ----
    for (int i = j; i < 2 * SEQ; i += NTHREADS) {
        int row = i >> 10, tt = i & (SEQ - 1);
        xs[i] = x[(blk * 2 + row) * SEQ + tt];
    }
    // register weights: k in [0,KR), pair kk = k-rows {2kk, 2kk+1}
    u64 w0[KRP], w1[KRP];
#pragma unroll
    for (int kk = 0; kk < KRP; kk++) {
        w0[kk] = pk2(Wr[(2 * kk) * NG + cA], Wr[(2 * kk + 1) * NG + cA]);
        w1[kk] = pk2(Wr[(2 * kk) * NG + cB], Wr[(2 * kk + 1) * NG + cB]);
    }
    // smem weights: k in [KR,128), per-thread contiguous 16B
    for (int kk = 0; kk < KSP; kk++) {
        const int k = KR + 2 * kk;
        ulonglong2 wv;
        wv.x = pk2(Wr[k * NG + cA], Wr[(k + 1) * NG + cA]);
        wv.y = pk2(Wr[k * NG + cB], Wr[(k + 1) * NG + cB]);
        W2[kk * NTHREADS + j] = wv;
    }
    // zero both h buffers
    for (int i = j; i < 256; i += NTHREADS) hbuf[i] = 0ull;
    __syncthreads();

    float c_state = 0.0f;

    for (int t = 0; t < SEQ; t++) {
        const u64* hc = hbuf + ((t & 1) << 7);       // current h, 128 u64

        // prefetch gate-table gathers for (unit u, row p)
        const int tok = xs[p * SEQ + t];
        const float* gr = g_G + (size_t)tok * NG + u;
        const float xg0 = gr[0];
        const float xg1 = gr[128];
        const float xg2 = gr[256];
        const float xg3 = gr[384];

        // ---- FMA phase: z for cols cA,cB over both rows ----
        u64 aA0 = 0ull, aA1 = 0ull, aB0 = 0ull, aB1 = 0ull;

        // REG section (36 pairs, h broadcast loads; ptxas hoists freely)
        auto reg_section = [&]() {
#pragma unroll
            for (int kk = 0; kk < KRP; kk++) {
                ulonglong2 hv = *(const ulonglong2*)(hc + 2 * kk);
                aA0 = fma2(w0[kk], hv.x, aA0);
                aA1 = fma2(w0[kk], hv.y, aA1);
                aB0 = fma2(w1[kk], hv.x, aB0);
                aB1 = fma2(w1[kk], hv.y, aB1);
            }
        };
        // SMEM section: double-buffered blocks of SB=4 weight pairs
        auto smem_section = [&]() {
            ulonglong2 wb[SB];
#pragma unroll
            for (int i = 0; i < SB; i++)
                wb[i] = W2[i * NTHREADS + j];
#pragma unroll
            for (int b = 0; b < NSB; b++) {
                ulonglong2 wn[SB];
                if (b + 1 < NSB) {
#pragma unroll
                    for (int i = 0; i < SB; i++)
                        wn[i] = W2[((b + 1) * SB + i) * NTHREADS + j];
                }
#pragma unroll
                for (int i = 0; i < SB; i++) {
                    const int kk = b * SB + i;
                    ulonglong2 hv = *(const ulonglong2*)(hc + 2 * (KRP + kk));
                    aA0 = fma2(wb[i].x, hv.x, aA0);
                    aA1 = fma2(wb[i].x, hv.y, aA1);
                    aB0 = fma2(wb[i].y, hv.x, aB0);
                    aB1 = fma2(wb[i].y, hv.y, aB1);
                }
                if (b + 1 < NSB) {
#pragma unroll
                    for (int i = 0; i < SB; i++)
                        wb[i] = wn[i];
                }
            }
        };

        if (smemFirst) { smem_section(); reg_section(); }
        else           { reg_section(); smem_section(); }

        float2 s;
        s = upk2(aA0); const float zA0 = s.x + s.y;   // gate p,   row 0
        s = upk2(aA1); const float zA1 = s.x + s.y;   // gate p,   row 1
        s = upk2(aB0); const float zB0 = s.x + s.y;   // gate p+2, row 0
        s = upk2(aB1); const float zB1 = s.x + s.y;   // gate p+2, row 1

        // ---- lane-pair exchange: collect all 4 gates for row p ----
        const float r1 = __shfl_xor_sync(0xffffffffu, p ? zA0 : zA1, 1);
        const float r2 = __shfl_xor_sync(0xffffffffu, p ? zB0 : zB1, 1);
        // even (p=0, row0): zi=zA0 zf=r1 zc=zB0 zo=r2
        // odd  (p=1, row1): zi=r1 zf=zA1 zc=r2 zo=zB1
        const float zi = (p ? r1  : zA0) + xg0;
        const float zf = (p ? zA1 : r1)  + xg1;
        const float zc = (p ? r2  : zB0) + xg2;
        const float zo = (p ? zB1 : r2)  + xg3;

        const float ig = sigmoidf(zi);
        const float fg = sigmoidf(zf);
        const float gg = fmaxf(zc, 0.0f);     // activation = relu
        const float og = sigmoidf(zo);
        c_state = fg * c_state + ig * gg;
        const float hn = og * fmaxf(c_state, 0.0f);

        // write h(t+1) into the other buffer, interleaved layout:
        // float word index = (u>>1)*4 + 2p + (u&1)
        float* hnx = (float*)(hbuf + (((t + 1) & 1) << 7));
        hnx[(u >> 1) * 4 + 2 * p + (u & 1)] = hn;
        __syncthreads();
    }

    // ---- dense head: final h lives in buffer 0 (SEQ is even) ----
    if (j < 4) {
        const int rr = j >> 1, oc = j & 1;
        const float* hb = (const float*)hbuf;      // buffer 0
        float acc = bd[oc];
        for (int uu = 0; uu < UNITS; uu++)
            acc += hb[(uu >> 1) * 4 + 2 * rr + (uu & 1)] * Wd[uu * 2 + oc];
        out[(blk * 2 + rr) * 2 + oc] = acc;
    }
}

// ---------------- launch ----------------
extern "C" void kernel_launch(void* const* d_in, const int* in_sizes, int n_in,
                              void* d_out, int out_size)
{
    const int*   x   = 0;
    const float *emb = 0, *Wk = 0, *Wr = 0, *bb = 0, *Wd = 0, *bd = 0;
    for (int i = 0; i < n_in; i++) {
        switch (in_sizes[i]) {                       // all sizes are distinct
            case BATCH * SEQ: x   = (const int*)  d_in[i]; break;  // 262144
            case VOCAB * EMB: emb = (const float*)d_in[i]; break;  // 2560000
            case EMB * NG:    Wk  = (const float*)d_in[i]; break;  // 131072
            case UNITS * NG:  Wr  = (const float*)d_in[i]; break;  // 65536
            case NG:          bb  = (const float*)d_in[i]; break;  // 512
            case UNITS * 2:   Wd  = (const float*)d_in[i]; break;  // 256
            case 2:           bd  = (const float*)d_in[i]; break;
        }
    }

    gbuild_kernel<<<VOCAB / VB, 512>>>(emb, Wk, bb);

    cudaFuncSetAttribute(lstm_kernel,
                         cudaFuncAttributeMaxDynamicSharedMemorySize, SMEM_TOTAL);
    lstm_kernel<<<NBLOCKS, NTHREADS, SMEM_TOTAL>>>(x, Wr, Wd, bd, (float*)d_out);
}

// round 13
// speedup vs baseline: 1.1488x; 1.1488x over previous
#include <cuda_runtime.h>
#include <cstdint>

typedef unsigned long long u64;

#define VOCAB   10000
#define EMB     256
#define UNITS   128
#define NG      512        // 4 * UNITS, gate order i,f,c,o
#define BATCH   256
#define SEQ     1024

#define NTHREADS 256
#define NBLOCKS  128       // 2 batch rows per block, one wave

// Precomputed gate table: G[v][c] = sum_e emb[v][e]*Wk[e][c] + b[c]  (20.5 MB)
__device__ float g_G[VOCAB * NG];

// ---------------- f32x2 helpers ----------------
__device__ __forceinline__ u64 fma2(u64 a, u64 b, u64 c) {
    u64 d;
    asm("fma.rn.f32x2 %0, %1, %2, %3;" : "=l"(d) : "l"(a), "l"(b), "l"(c));
    return d;
}
__device__ __forceinline__ u64 pk2(float x, float y) {
    u64 r;
    asm("mov.b64 %0, {%1, %2};" : "=l"(r) : "f"(x), "f"(y));
    return r;
}
__device__ __forceinline__ float2 upk2(u64 v) {
    float2 r;
    asm("mov.b64 {%0, %1}, %2;" : "=f"(r.x), "=f"(r.y) : "l"(v));
    return r;
}
__device__ __forceinline__ float sigmoidf(float x) {
    return __fdividef(1.0f, 1.0f + __expf(-x));
}

// ---------------- Kernel 1: G = emb @ Wk + b ----------------
#define VB 16
__global__ void __launch_bounds__(512)
gbuild_kernel(const float* __restrict__ emb, const float* __restrict__ Wk,
              const float* __restrict__ b)
{
    __shared__ float es[VB][EMB];
    const int c  = threadIdx.x;
    const int v0 = blockIdx.x * VB;

    for (int i = c; i < VB * EMB; i += 512)
        es[i / EMB][i % EMB] = emb[v0 * EMB + i];
    __syncthreads();

    float acc[VB];
#pragma unroll
    for (int v = 0; v < VB; v++) acc[v] = 0.0f;

    for (int e = 0; e < EMB; e += 4) {
        const float w0 = Wk[(e + 0) * NG + c];
        const float w1 = Wk[(e + 1) * NG + c];
        const float w2 = Wk[(e + 2) * NG + c];
        const float w3 = Wk[(e + 3) * NG + c];
#pragma unroll
        for (int v = 0; v < VB; v++) {
            float4 ev = *(const float4*)&es[v][e];
            acc[v] += ev.x * w0 + ev.y * w1 + ev.z * w2 + ev.w * w3;
        }
    }
    const float bc = b[c];
#pragma unroll
    for (int v = 0; v < VB; v++)
        g_G[(v0 + v) * NG + c] = acc[v] + bc;
}

// ---------------- Kernel 2: persistent LSTM recurrence ----------------
// 128 CTAs x 256 threads, 2 batch rows per CTA.
// Thread j: warp w=j>>5, lane l=j&31; kh = l>>4 (k-half), unit
// u = w*16 + (l&15). The thread computes partial z for ALL FOUR gate
// columns {u, 128+u, 256+u, 384+u} of its unit over k in [64kh,64kh+64),
// both rows. One shfl.xor(16) partial-sum exchange then gives the full
// 4 gates; thread kh=r runs the nonlinearity + c_state for row r.
// No z smem, no gate shuffle network, ONE __syncthreads per step.
//
// Weights per thread: 128 u64 pairs total; gates 0,1 fully + gate 2
// first half in registers (160 regs), gate 2 second half + gate 3 in
// smem as per-lane ulonglong2 (conflict-free LDS.128).
//
// h double-buffered, pair-interleaved with a 16B skew between k-halves
// so the two broadcast addresses of an LDS.128 hit disjoint banks:
//   u64 idx(kp,row) = 2*kp + row + 2*(kp>=32),  kp = k-pair = u>>1
#define WT_ENTRIES 24                       // ulonglong2 slots per thread
#define WT_BYTES  (WT_ENTRIES * NTHREADS * 16)   // 98304 B
#define HB_OFF    WT_BYTES
#define HB_STRIDE 132                       // u64 per h buffer (130 + pad)
#define HB_BYTES  (2 * HB_STRIDE * 8)       // 2112 B
#define XS_OFF    (HB_OFF + HB_BYTES)
#define SMEM_TOTAL (XS_OFF + 2 * SEQ * 4)

__global__ void __launch_bounds__(NTHREADS, 1)
lstm_kernel(const int* __restrict__ x, const float* __restrict__ Wr,
            const float* __restrict__ Wd, const float* __restrict__ bd,
            float* __restrict__ out)
{
    extern __shared__ char smem[];
    ulonglong2* Wt   = (ulonglong2*)smem;          // [24][256]
    u64*        hbuf = (u64*)(smem + HB_OFF);      // [2][132]
    int*        xs   = (int*)(smem + XS_OFF);

    const int j   = threadIdx.x;
    const int blk = blockIdx.x;
    const int l   = j & 31;
    const int kh  = l >> 4;                 // k-half 0/1
    const int u   = (j >> 5) * 16 + (l & 15);   // unit 0..127
    const int c0  = u, c1 = 128 + u, c2 = 256 + u, c3 = 384 + u;
    const int kb  = 64 * kh;                // k base

    // ---- one-time setup ----
    for (int i = j; i < 2 * SEQ; i += NTHREADS) {
        int row = i >> 10, tt = i & (SEQ - 1);
        xs[i] = x[(blk * 2 + row) * SEQ + tt];
    }
    // register weights: gates 0,1 all 32 pairs; gate 2 pairs 0..15
    u64 wr0[32], wr1[32], wr2[16];
#pragma unroll
    for (int kk = 0; kk < 32; kk++) {
        const int k = kb + 2 * kk;
        wr0[kk] = pk2(Wr[k * NG + c0], Wr[(k + 1) * NG + c0]);
        wr1[kk] = pk2(Wr[k * NG + c1], Wr[(k + 1) * NG + c1]);
    }
#pragma unroll
    for (int kk = 0; kk < 16; kk++) {
        const int k = kb + 2 * kk;
        wr2[kk] = pk2(Wr[k * NG + c2], Wr[(k + 1) * NG + c2]);
    }
    // smem weights: Wt[m][j]: m 0..7 = gate2 pairs {16+2m,17+2m};
    //               m 8..23 = gate3 pairs {2(m-8), 2(m-8)+1}
    for (int m = 0; m < 8; m++) {
        const int k = kb + 2 * (16 + 2 * m);
        ulonglong2 wv;
        wv.x = pk2(Wr[k * NG + c2],       Wr[(k + 1) * NG + c2]);
        wv.y = pk2(Wr[(k + 2) * NG + c2], Wr[(k + 3) * NG + c2]);
        Wt[m * NTHREADS + j] = wv;
    }
    for (int m = 0; m < 16; m++) {
        const int k = kb + 2 * (2 * m);
        ulonglong2 wv;
        wv.x = pk2(Wr[k * NG + c3],       Wr[(k + 1) * NG + c3]);
        wv.y = pk2(Wr[(k + 2) * NG + c3], Wr[(k + 3) * NG + c3]);
        Wt[(8 + m) * NTHREADS + j] = wv;
    }
    // zero both h buffers
    for (int i = j; i < 2 * HB_STRIDE; i += NTHREADS) hbuf[i] = 0ull;
    __syncthreads();

    float c_state = 0.0f;                   // row kh of this unit

    for (int t = 0; t < SEQ; t++) {
        // base of my k-half in the current buffer: 2*(32kh) + skew(2kh)
        const u64* hbase = hbuf + ((t & 1) ? HB_STRIDE : 0) + 66 * kh;

        // prefetch gate-table gathers for (u, row kh)
        const int tok = xs[kh * SEQ + t];
        const float* gr = g_G + (size_t)tok * NG + u;
        const float xg0 = gr[0];
        const float xg1 = gr[128];
        const float xg2 = gr[256];
        const float xg3 = gr[384];

        // ---- FMA phase: 4 gates x 2 rows over my 32 k-pairs ----
        u64 a0r0 = 0ull, a0r1 = 0ull, a1r0 = 0ull, a1r1 = 0ull;
        u64 a2r0 = 0ull, a2r1 = 0ull, a3r0 = 0ull, a3r1 = 0ull;
#pragma unroll
        for (int i = 0; i < 16; i++) {
            // pairs kk=2i (hva) and kk=2i+1 (hvb); .x=row0, .y=row1
            ulonglong2 hva = *(const ulonglong2*)(hbase + 4 * i);
            ulonglong2 hvb = *(const ulonglong2*)(hbase + 4 * i + 2);

            a0r0 = fma2(wr0[2 * i],     hva.x, a0r0);
            a0r1 = fma2(wr0[2 * i],     hva.y, a0r1);
            a0r0 = fma2(wr0[2 * i + 1], hvb.x, a0r0);
            a0r1 = fma2(wr0[2 * i + 1], hvb.y, a0r1);

            a1r0 = fma2(wr1[2 * i],     hva.x, a1r0);
            a1r1 = fma2(wr1[2 * i],     hva.y, a1r1);
            a1r0 = fma2(wr1[2 * i + 1], hvb.x, a1r0);
            a1r1 = fma2(wr1[2 * i + 1], hvb.y, a1r1);

            u64 w2a, w2b;
            if (i < 8) { w2a = wr2[2 * i]; w2b = wr2[2 * i + 1]; }
            else {
                ulonglong2 wv = Wt[(i - 8) * NTHREADS + j];
                w2a = wv.x; w2b = wv.y;
            }
            a2r0 = fma2(w2a, hva.x, a2r0);
            a2r1 = fma2(w2a, hva.y, a2r1);
            a2r0 = fma2(w2b, hvb.x, a2r0);
            a2r1 = fma2(w2b, hvb.y, a2r1);

            ulonglong2 wv3 = Wt[(8 + i) * NTHREADS + j];
            a3r0 = fma2(wv3.x, hva.x, a3r0);
            a3r1 = fma2(wv3.x, hva.y, a3r1);
            a3r0 = fma2(wv3.y, hvb.x, a3r0);
            a3r1 = fma2(wv3.y, hvb.y, a3r1);
        }

        // half-sums: p[g][row]
        float2 s;
        s = upk2(a0r0); const float p0r0 = s.x + s.y;
        s = upk2(a0r1); const float p0r1 = s.x + s.y;
        s = upk2(a1r0); const float p1r0 = s.x + s.y;
        s = upk2(a1r1); const float p1r1 = s.x + s.y;
        s = upk2(a2r0); const float p2r0 = s.x + s.y;
        s = upk2(a2r1); const float p2r1 = s.x + s.y;
        s = upk2(a3r0); const float p3r0 = s.x + s.y;
        s = upk2(a3r1); const float p3r1 = s.x + s.y;

        // exchange: send my partial for the OTHER row; receive partner's
        // partial for MY row; add -> full z for row kh.
        const float own0 = kh ? p0r1 : p0r0, oth0 = kh ? p0r0 : p0r1;
        const float own1 = kh ? p1r1 : p1r0, oth1 = kh ? p1r0 : p1r1;
        const float own2 = kh ? p2r1 : p2r0, oth2 = kh ? p2r0 : p2r1;
        const float own3 = kh ? p3r1 : p3r0, oth3 = kh ? p3r0 : p3r1;
        const float z0 = own0 + __shfl_xor_sync(0xffffffffu, oth0, 16);
        const float z1 = own1 + __shfl_xor_sync(0xffffffffu, oth1, 16);
        const float z2 = own2 + __shfl_xor_sync(0xffffffffu, oth2, 16);
        const float z3 = own3 + __shfl_xor_sync(0xffffffffu, oth3, 16);

        // ---- gates for (unit u, row kh) ----
        const float zi = z0 + xg0;
        const float zf = z1 + xg1;
        const float zc = z2 + xg2;
        const float zo = z3 + xg3;
        const float ig = sigmoidf(zi);
        const float fg = sigmoidf(zf);
        const float gg = fmaxf(zc, 0.0f);   // activation = relu
        const float og = sigmoidf(zo);
        c_state = fg * c_state + ig * gg;
        const float hn = og * fmaxf(c_state, 0.0f);

        // store h(t+1): kp = u>>1; float idx = 4*kp + 2*kh + (u&1) + 4*(kp>=32)
        float* hnx = (float*)(hbuf + (((t + 1) & 1) ? HB_STRIDE : 0));
        hnx[4 * (u >> 1) + 2 * kh + (u & 1) + ((u >= 64) ? 4 : 0)] = hn;
        __syncthreads();
    }

    // ---- dense head: final h lives in buffer 0 (SEQ is even) ----
    if (j < 4) {
        const int rr = j >> 1, oc = j & 1;
        const float* hb = (const float*)hbuf;     // buffer 0
        float acc = bd[oc];
        for (int uu = 0; uu < UNITS; uu++)
            acc += hb[4 * (uu >> 1) + 2 * rr + (uu & 1) + ((uu >= 64) ? 4 : 0)]
                 * Wd[uu * 2 + oc];
        out[(blk * 2 + rr) * 2 + oc] = acc;
    }
}

// ---------------- launch ----------------
extern "C" void kernel_launch(void* const* d_in, const int* in_sizes, int n_in,
                              void* d_out, int out_size)
{
    const int*   x   = 0;
    const float *emb = 0, *Wk = 0, *Wr = 0, *bb = 0, *Wd = 0, *bd = 0;
    for (int i = 0; i < n_in; i++) {
        switch (in_sizes[i]) {                       // all sizes are distinct
            case BATCH * SEQ: x   = (const int*)  d_in[i]; break;  // 262144
            case VOCAB * EMB: emb = (const float*)d_in[i]; break;  // 2560000
            case EMB * NG:    Wk  = (const float*)d_in[i]; break;  // 131072
            case UNITS * NG:  Wr  = (const float*)d_in[i]; break;  // 65536
            case NG:          bb  = (const float*)d_in[i]; break;  // 512
            case UNITS * 2:   Wd  = (const float*)d_in[i]; break;  // 256
            case 2:           bd  = (const float*)d_in[i]; break;
        }
    }

    gbuild_kernel<<<VOCAB / VB, 512>>>(emb, Wk, bb);

    cudaFuncSetAttribute(lstm_kernel,
                         cudaFuncAttributeMaxDynamicSharedMemorySize, SMEM_TOTAL);
    lstm_kernel<<<NBLOCKS, NTHREADS, SMEM_TOTAL>>>(x, Wr, Wd, bd, (float*)d_out);
}